// round 14
// baseline (speedup 1.0000x reference)
#include <cuda_runtime.h>
#include <cuda_bf16.h>
#include <mma.h>

using namespace nvcuda;

#define BB 16
#define NN 256
#define DM 512
#define HH 8
#define DK 64

// Scratch (allocation-free rule: __device__ globals)
__device__ float g_q[BB*NN*DM];
__device__ float g_k[BB*NN*DM];
__device__ float g_v[BB*NN*DM];
__device__ float g_bias[BB*HH*NN*NN];   // clamped relu(w_g)
__device__ float g_att[BB*NN*DM];       // attention output pre-Wo

__constant__ float c_dim[8] = {
    1.0f, 0.421696503f, 0.177827941f, 0.0749894209f,
    0.0316227766f, 0.0133352143f, 0.00562341325f, 0.00237137371f};

#define GM 4096
#define GN 512
#define GK 512
#define NKT (GK / 16)   // 32

// convert 8 floats -> hi/lo bf16x2 quads, one 16B STS each
__device__ __forceinline__ void cvt_store8(
    __nv_bfloat16* dst_hi, __nv_bfloat16* dst_lo, const float* v)
{
    __nv_bfloat162 h[4], l[4];
    #pragma unroll
    for (int i = 0; i < 4; i++) {
        float2 f = make_float2(v[2*i], v[2*i + 1]);
        h[i] = __float22bfloat162_rn(f);
        float2 hf = __bfloat1622float2(h[i]);
        l[i] = __float22bfloat162_rn(make_float2(f.x - hf.x, f.y - hf.y));
    }
    *reinterpret_cast<uint4*>(dst_hi) = *reinterpret_cast<const uint4*>(h);
    *reinterpret_cast<uint4*>(dst_lo) = *reinterpret_cast<const uint4*>(l);
}
__device__ __forceinline__ void cvt_store16(
    __nv_bfloat16* dst_hi, __nv_bfloat16* dst_lo, const float* v)
{
    cvt_store8(dst_hi, dst_lo, v);
    cvt_store8(dst_hi + 8, dst_lo + 8, v + 8);
}

// ---------------------------------------------------------------------------
// 64x128 GEMM tile, bf16 3-term split, double-buffered.
// __launch_bounds__(256,3): reg-cap 85 -> 3 CTAs/SM (24 warps) for latency hiding.
// ---------------------------------------------------------------------------
struct GemmSmem64 {
    __nv_bfloat16 Ah[64][24];
    __nv_bfloat16 Al[64][24];
    __nv_bfloat16 Bh[16][136];
    __nv_bfloat16 Bl[16][136];
};

__device__ __forceinline__ void gemm_tile64(
    GemmSmem64* sm,
    const float* __restrict__ A, const float* __restrict__ W,
    const float* __restrict__ bias, float* __restrict__ C,
    int bm, int bn)
{
    const int tid  = threadIdx.x;
    const int warp = tid >> 5;
    const int lane = tid & 31;
    const int wm   = warp >> 2;     // 0..1 -> rows
    const int wn   = warp & 3;      // 0..3 -> cols

    const int ar = tid >> 1;              // 0..127 (only tid<128 stages A)
    const int ac = (tid & 1) * 8;
    const int br = tid >> 4;
    const int bc = (tid & 15) * 8;
    const bool doA = (tid < 128);

    wmma::fragment<wmma::accumulator, 16, 16, 16, float> acc[2][2];
    #pragma unroll
    for (int i = 0; i < 2; i++)
        #pragma unroll
        for (int j = 0; j < 2; j++)
            wmma::fill_fragment(acc[i][j], 0.0f);

    float va[8], vb[8];
    {
        if (doA) {
            const float* ap = &A[(size_t)(bm + ar) * GK + ac];
            float4 f0 = *reinterpret_cast<const float4*>(ap);
            float4 f1 = *reinterpret_cast<const float4*>(ap + 4);
            va[0]=f0.x; va[1]=f0.y; va[2]=f0.z; va[3]=f0.w;
            va[4]=f1.x; va[5]=f1.y; va[6]=f1.z; va[7]=f1.w;
        }
        const float* bp = &W[(size_t)br * GN + bn + bc];
        float4 g0 = *reinterpret_cast<const float4*>(bp);
        float4 g1 = *reinterpret_cast<const float4*>(bp + 4);
        vb[0]=g0.x; vb[1]=g0.y; vb[2]=g0.z; vb[3]=g0.w;
        vb[4]=g1.x; vb[5]=g1.y; vb[6]=g1.z; vb[7]=g1.w;
        if (doA) cvt_store8(&sm[0].Ah[ar][ac], &sm[0].Al[ar][ac], va);
        cvt_store8(&sm[0].Bh[br][bc], &sm[0].Bl[br][bc], vb);
    }
    __syncthreads();

    for (int kt = 0; kt < NKT; kt++) {
        const int cur = kt & 1;
        const bool more = (kt + 1 < NKT);
        if (more) {
            const int k0 = (kt + 1) * 16;
            if (doA) {
                const float* ap = &A[(size_t)(bm + ar) * GK + k0 + ac];
                float4 f0 = *reinterpret_cast<const float4*>(ap);
                float4 f1 = *reinterpret_cast<const float4*>(ap + 4);
                va[0]=f0.x; va[1]=f0.y; va[2]=f0.z; va[3]=f0.w;
                va[4]=f1.x; va[5]=f1.y; va[6]=f1.z; va[7]=f1.w;
            }
            const float* bp = &W[(size_t)(k0 + br) * GN + bn + bc];
            float4 g0 = *reinterpret_cast<const float4*>(bp);
            float4 g1 = *reinterpret_cast<const float4*>(bp + 4);
            vb[0]=g0.x; vb[1]=g0.y; vb[2]=g0.z; vb[3]=g0.w;
            vb[4]=g1.x; vb[5]=g1.y; vb[6]=g1.z; vb[7]=g1.w;
        }
        {
            GemmSmem64& s = sm[cur];
            wmma::fragment<wmma::matrix_a, 16, 16, 16, __nv_bfloat16,
                           wmma::row_major> ah[2], al[2];
            wmma::fragment<wmma::matrix_b, 16, 16, 16, __nv_bfloat16,
                           wmma::row_major> bh[2], bl[2];
            #pragma unroll
            for (int i = 0; i < 2; i++) {
                wmma::load_matrix_sync(ah[i], &s.Ah[wm * 32 + i * 16][0], 24);
                wmma::load_matrix_sync(al[i], &s.Al[wm * 32 + i * 16][0], 24);
            }
            #pragma unroll
            for (int j = 0; j < 2; j++) {
                wmma::load_matrix_sync(bh[j], &s.Bh[0][wn * 32 + j * 16], 136);
                wmma::load_matrix_sync(bl[j], &s.Bl[0][wn * 32 + j * 16], 136);
            }
            #pragma unroll
            for (int i = 0; i < 2; i++)
                #pragma unroll
                for (int j = 0; j < 2; j++) {
                    wmma::mma_sync(acc[i][j], ah[i], bh[j], acc[i][j]);
                    wmma::mma_sync(acc[i][j], ah[i], bl[j], acc[i][j]);
                    wmma::mma_sync(acc[i][j], al[i], bh[j], acc[i][j]);
                }
        }
        if (more) {
            if (doA) cvt_store8(&sm[cur ^ 1].Ah[ar][ac], &sm[cur ^ 1].Al[ar][ac], va);
            cvt_store8(&sm[cur ^ 1].Bh[br][bc], &sm[cur ^ 1].Bl[br][bc], vb);
        }
        __syncthreads();
    }

    float* epib = reinterpret_cast<float*>(sm) + warp * 288;
    const int er = lane >> 1;
    const int ec = (lane & 1) * 8;
    #pragma unroll
    for (int i = 0; i < 2; i++)
        #pragma unroll
        for (int j = 0; j < 2; j++) {
            wmma::store_matrix_sync(epib, acc[i][j], 18, wmma::mem_row_major);
            __syncwarp();
            const int row = bm + wm * 32 + i * 16 + er;
            const int col = bn + wn * 32 + j * 16 + ec;
            float4 b0 = *reinterpret_cast<const float4*>(&bias[col]);
            float4 b1 = *reinterpret_cast<const float4*>(&bias[col + 4]);
            const float* ep = &epib[er * 18 + ec];
            float4 o0 = {ep[0] + b0.x, ep[1] + b0.y, ep[2] + b0.z, ep[3] + b0.w};
            float4 o1 = {ep[4] + b1.x, ep[5] + b1.y, ep[6] + b1.z, ep[7] + b1.w};
            *reinterpret_cast<float4*>(&C[(size_t)row * GN + col])     = o0;
            *reinterpret_cast<float4*>(&C[(size_t)row * GN + col + 4]) = o1;
            __syncwarp();
        }
}

// QKV: 64x128 tiles, blockIdx.z selects triple. (4,64,3) = 768 blocks.
__global__ __launch_bounds__(256, 3) void gemm_qkv64(
    const float* __restrict__ xq, const float* __restrict__ xk,
    const float* __restrict__ xv,
    const float* __restrict__ Wq, const float* __restrict__ Wk,
    const float* __restrict__ Wv,
    const float* __restrict__ bq, const float* __restrict__ bk,
    const float* __restrict__ bv,
    float* __restrict__ oq, float* __restrict__ ok, float* __restrict__ ov)
{
    __shared__ GemmSmem64 sm[2];
    const float *A, *W, *bias;
    float* C;
    if (blockIdx.z == 0)      { A = xq; W = Wq; bias = bq; C = oq; }
    else if (blockIdx.z == 1) { A = xk; W = Wk; bias = bk; C = ok; }
    else                      { A = xv; W = Wv; bias = bv; C = ov; }
    gemm_tile64(sm, A, W, bias, C, blockIdx.y * 64, blockIdx.x * 128);
}

__global__ __launch_bounds__(256, 3) void gemm_one64(
    const float* __restrict__ A, const float* __restrict__ W,
    const float* __restrict__ bias, float* __restrict__ C)
{
    __shared__ GemmSmem64 sm[2];
    gemm_tile64(sm, A, W, bias, C, blockIdx.y * 64, blockIdx.x * 128);
}

// ---------------------------------------------------------------------------
// Geometric weights (unchanged)
// ---------------------------------------------------------------------------
__global__ __launch_bounds__(256) void geo_bias(
    const float* __restrict__ box, const float* __restrict__ WGw,
    const float* __restrict__ WGb)
{
    __shared__ float sW[HH * 64];
    __shared__ float sB[HH];
    const int b = blockIdx.y;
    const int q = blockIdx.x;
    const int m = threadIdx.x;

    sW[m] = WGw[m];
    sW[m + 256] = WGw[m + 256];
    if (m < HH) sB[m] = WGb[m];
    __syncthreads();

    const float* bq = box + ((size_t)b * NN + q) * 4;
    const float x0q = bq[0], y0q = bq[1], x1q = bq[2], y1q = bq[3];
    const float cxq = (x0q + x1q) * 0.5f, cyq = (y0q + y1q) * 0.5f;
    const float wq = x1q - x0q + 1.0f,   hq = y1q - y0q + 1.0f;

    const float* bmp = box + ((size_t)b * NN + m) * 4;
    const float x0m = bmp[0], y0m = bmp[1], x1m = bmp[2], y1m = bmp[3];
    const float cxm = (x0m + x1m) * 0.5f, cym = (y0m + y1m) * 0.5f;
    const float wm = x1m - x0m + 1.0f,    hm = y1m - y0m + 1.0f;

    float delta[4];
    delta[0] = logf(fmaxf(fabsf((cxq - cxm) / wq), 0.001f));
    delta[1] = logf(fmaxf(fabsf((cyq - cym) / hq), 0.001f));
    delta[2] = logf(wq / wm);
    delta[3] = logf(hq / hm);

    float acc[HH];
    #pragma unroll
    for (int h = 0; h < HH; h++) acc[h] = sB[h];

    #pragma unroll
    for (int p = 0; p < 4; p++) {
        #pragma unroll
        for (int f = 0; f < 8; f++) {
            float ang = 100.0f * delta[p] * c_dim[f];
            float r = ang - 6.28318530717958647692f *
                            rintf(ang * 0.15915494309189533577f);
            float s, c;
            sincosf(r, &s, &c);
            const int idx = p * 8 + f;
            #pragma unroll
            for (int h = 0; h < HH; h++)
                acc[h] += s * sW[h * 64 + idx] + c * sW[h * 64 + 32 + idx];
        }
    }

    #pragma unroll
    for (int h = 0; h < HH; h++) {
        g_bias[(((size_t)b * HH + h) * NN + q) * NN + m] =
            fmaxf(acc[h], 1e-6f);
    }
}

// ---------------------------------------------------------------------------
// Tensor-core attention with aliased smem buffers (~91KB -> 2 CTAs/SM)
// ---------------------------------------------------------------------------
struct AttnSmem {
    __nv_bfloat16 Qh[64][72],  Ql[64][72];
    __nv_bfloat16 KPh[64][72], KPl[64][72];   // K tile, then P tile
    __nv_bfloat16 Vh[64][72],  Vl[64][72];
    float SOd[64][68];                        // scores, then Od
    float Os [64][68];
    float M[64], L[64], Sc[64];
};

__global__ __launch_bounds__(256, 2) void attn3(const int* __restrict__ mask)
{
    extern __shared__ char smraw[];
    AttnSmem& sm = *reinterpret_cast<AttnSmem*>(smraw);

    const int qt = blockIdx.x, h = blockIdx.y, b = blockIdx.z;
    const int qb = qt * 64;
    const int tid  = threadIdx.x;
    const int warp = tid >> 5;
    const int wm   = warp >> 2;   // 0..1
    const int wn   = warp & 3;    // 0..3
    const int rq   = tid >> 2;    // 0..63
    const int sub  = tid & 3;
    const int d0   = sub * 16;

    {
        const float* qp = g_q + ((size_t)(b * NN + qb + rq)) * DM + h * DK + d0;
        float v[16];
        #pragma unroll
        for (int g = 0; g < 4; g++) {
            float4 f = *reinterpret_cast<const float4*>(qp + g * 4);
            v[g*4+0] = f.x * 0.125f; v[g*4+1] = f.y * 0.125f;
            v[g*4+2] = f.z * 0.125f; v[g*4+3] = f.w * 0.125f;
        }
        cvt_store16(&sm.Qh[rq][d0], &sm.Ql[rq][d0], v);
    }
    if (tid < 64) { sm.M[tid] = -3.0e38f; sm.L[tid] = 0.0f; }
    #pragma unroll
    for (int j = 0; j < 16; j++) sm.Os[rq][d0 + j] = 0.0f;

    const int* mk = mask + b * NN;
    const float* wgrow = g_bias + ((size_t)(b * HH + h) * NN + qb) * NN + (size_t)rq * NN;

    for (int kt = 0; kt < 4; kt++) {
        const int kg0 = kt * 64;
        __syncthreads();   // protects K restage vs prior PV reads of P
        {
            float v[16];
            const float* kp = g_k + ((size_t)(b * NN + kg0 + rq)) * DM + h * DK + d0;
            #pragma unroll
            for (int g = 0; g < 4; g++) {
                float4 f = *reinterpret_cast<const float4*>(kp + g * 4);
                v[g*4+0]=f.x; v[g*4+1]=f.y; v[g*4+2]=f.z; v[g*4+3]=f.w;
            }
            cvt_store16(&sm.KPh[rq][d0], &sm.KPl[rq][d0], v);
            const float* vp = g_v + ((size_t)(b * NN + kg0 + rq)) * DM + h * DK + d0;
            #pragma unroll
            for (int g = 0; g < 4; g++) {
                float4 f = *reinterpret_cast<const float4*>(vp + g * 4);
                v[g*4+0]=f.x; v[g*4+1]=f.y; v[g*4+2]=f.z; v[g*4+3]=f.w;
            }
            cvt_store16(&sm.Vh[rq][d0], &sm.Vl[rq][d0], v);
        }
        __syncthreads();

        // scores: S = Q·K^T
        {
            wmma::fragment<wmma::accumulator, 16, 16, 16, float> sa[2];
            #pragma unroll
            for (int i = 0; i < 2; i++) wmma::fill_fragment(sa[i], 0.0f);
            #pragma unroll
            for (int kk = 0; kk < 4; kk++) {
                wmma::fragment<wmma::matrix_b, 16, 16, 16, __nv_bfloat16,
                               wmma::col_major> bh, bl;
                wmma::load_matrix_sync(bh, &sm.KPh[wn * 16][kk * 16], 72);
                wmma::load_matrix_sync(bl, &sm.KPl[wn * 16][kk * 16], 72);
                #pragma unroll
                for (int i = 0; i < 2; i++) {
                    wmma::fragment<wmma::matrix_a, 16, 16, 16, __nv_bfloat16,
                                   wmma::row_major> ah, al;
                    wmma::load_matrix_sync(ah, &sm.Qh[wm * 32 + i * 16][kk * 16], 72);
                    wmma::load_matrix_sync(al, &sm.Ql[wm * 32 + i * 16][kk * 16], 72);
                    wmma::mma_sync(sa[i], ah, bh, sa[i]);
                    wmma::mma_sync(sa[i], ah, bl, sa[i]);
                    wmma::mma_sync(sa[i], al, bh, sa[i]);
                }
            }
            #pragma unroll
            for (int i = 0; i < 2; i++)
                wmma::store_matrix_sync(&sm.SOd[wm * 32 + i * 16][wn * 16], sa[i],
                                        68, wmma::mem_row_major);
        }
        __syncthreads();   // scores done -> K region reusable for P

        // online softmax: read S, write P (over K region)
        {
            const int4* mi = reinterpret_cast<const int4*>(&mk[kg0 + d0]);
            int mv[16];
            #pragma unroll
            for (int g = 0; g < 4; g++) {
                int4 m4 = mi[g];
                mv[g*4+0]=m4.x; mv[g*4+1]=m4.y; mv[g*4+2]=m4.z; mv[g*4+3]=m4.w;
            }
            float s[16];
            float mt = -3.0e38f;
            #pragma unroll
            for (int j = 0; j < 16; j++) {
                float sv = sm.SOd[rq][d0 + j];
                if (mv[j] == 0) sv = -1e9f;
                s[j] = sv;
                mt = fmaxf(mt, sv);
            }
            mt = fmaxf(mt, __shfl_xor_sync(0xffffffffu, mt, 1));
            mt = fmaxf(mt, __shfl_xor_sync(0xffffffffu, mt, 2));
            if (sub == 0) {
                float m_old = sm.M[rq];
                float m_new = fmaxf(m_old, mt);
                sm.M[rq] = m_new;
                float sc = __expf(m_old - m_new);
                sm.Sc[rq] = sc;
                sm.L[rq] *= sc;
            }
            __syncwarp();
            const float mq = sm.M[rq];
            float p[16];
            float psum = 0.0f;
            const float* wgp = wgrow + kg0 + d0;
            #pragma unroll
            for (int g = 0; g < 4; g++) {
                float4 w4 = *reinterpret_cast<const float4*>(wgp + g * 4);
                float wv[4] = {w4.x, w4.y, w4.z, w4.w};
                #pragma unroll
                for (int u = 0; u < 4; u++) {
                    float pv = wv[u] * __expf(s[g*4+u] - mq);
                    p[g*4+u] = pv;
                    psum += pv;
                }
            }
            cvt_store16(&sm.KPh[rq][d0], &sm.KPl[rq][d0], p);
            psum += __shfl_xor_sync(0xffffffffu, psum, 1);
            psum += __shfl_xor_sync(0xffffffffu, psum, 2);
            if (sub == 0) sm.L[rq] += psum;
        }
        __syncthreads();   // softmax done -> S region reusable for Od

        // PV: Od = P·V (over S region)
        {
            wmma::fragment<wmma::accumulator, 16, 16, 16, float> pa[2];
            #pragma unroll
            for (int i = 0; i < 2; i++) wmma::fill_fragment(pa[i], 0.0f);
            #pragma unroll
            for (int kk = 0; kk < 4; kk++) {
                wmma::fragment<wmma::matrix_b, 16, 16, 16, __nv_bfloat16,
                               wmma::row_major> bh, bl;
                wmma::load_matrix_sync(bh, &sm.Vh[kk * 16][wn * 16], 72);
                wmma::load_matrix_sync(bl, &sm.Vl[kk * 16][wn * 16], 72);
                #pragma unroll
                for (int i = 0; i < 2; i++) {
                    wmma::fragment<wmma::matrix_a, 16, 16, 16, __nv_bfloat16,
                                   wmma::row_major> ah, al;
                    wmma::load_matrix_sync(ah, &sm.KPh[wm * 32 + i * 16][kk * 16], 72);
                    wmma::load_matrix_sync(al, &sm.KPl[wm * 32 + i * 16][kk * 16], 72);
                    wmma::mma_sync(pa[i], ah, bh, pa[i]);
                    wmma::mma_sync(pa[i], ah, bl, pa[i]);
                    wmma::mma_sync(pa[i], al, bh, pa[i]);
                }
            }
            #pragma unroll
            for (int i = 0; i < 2; i++)
                wmma::store_matrix_sync(&sm.SOd[wm * 32 + i * 16][wn * 16], pa[i],
                                        68, wmma::mem_row_major);
        }
        __syncthreads();

        // merge: Os = Os*scale + Od
        {
            const float sc = sm.Sc[rq];
            #pragma unroll
            for (int j = 0; j < 16; j++)
                sm.Os[rq][d0 + j] = sm.Os[rq][d0 + j] * sc + sm.SOd[rq][d0 + j];
        }
    }
    __syncthreads();

    {
        const float inv = 1.0f / sm.L[rq];
        float* op = g_att + ((size_t)(b * NN + qb + rq)) * DM + h * DK + d0;
        #pragma unroll
        for (int g = 0; g < 4; g++) {
            float4 o;
            o.x = sm.Os[rq][d0 + g*4 + 0] * inv;
            o.y = sm.Os[rq][d0 + g*4 + 1] * inv;
            o.z = sm.Os[rq][d0 + g*4 + 2] * inv;
            o.w = sm.Os[rq][d0 + g*4 + 3] * inv;
            *reinterpret_cast<float4*>(op + g * 4) = o;
        }
    }
}

// ---------------------------------------------------------------------------
extern "C" void kernel_launch(void* const* d_in, const int* in_sizes, int n_in,
                              void* d_out, int out_size)
{
    const float* xq  = (const float*)d_in[0];
    const float* xk  = (const float*)d_in[1];
    const float* xv  = (const float*)d_in[2];
    const float* box = (const float*)d_in[3];
    const int*   msk = (const int*)  d_in[4];
    const float* Wq  = (const float*)d_in[5];
    const float* bq  = (const float*)d_in[6];
    const float* Wk  = (const float*)d_in[7];
    const float* bk  = (const float*)d_in[8];
    const float* Wv  = (const float*)d_in[9];
    const float* bv  = (const float*)d_in[10];
    const float* Wo  = (const float*)d_in[11];
    const float* bo  = (const float*)d_in[12];
    const float* WGw = (const float*)d_in[13];
    const float* WGb = (const float*)d_in[14];

    float* out = (float*)d_out;

    void *pq, *pk, *pv, *pa;
    cudaGetSymbolAddress(&pq, g_q);
    cudaGetSymbolAddress(&pk, g_k);
    cudaGetSymbolAddress(&pv, g_v);
    cudaGetSymbolAddress(&pa, g_att);

    static cudaStream_t s_geo = nullptr;
    static cudaEvent_t  e_fork = nullptr, e_join = nullptr;
    if (s_geo == nullptr) {
        cudaStreamCreateWithFlags(&s_geo, cudaStreamNonBlocking);
        cudaEventCreateWithFlags(&e_fork, cudaEventDisableTiming);
        cudaEventCreateWithFlags(&e_join, cudaEventDisableTiming);
        cudaFuncSetAttribute(attn3,
            cudaFuncAttributeMaxDynamicSharedMemorySize, (int)sizeof(AttnSmem));
    }

    dim3 qkvgrid(GN / 128, GM / 64, 3);     // (4, 64, 3) = 768 blocks
    dim3 ogrid  (GN / 128, GM / 64);        // (4, 64)    = 256 blocks

    cudaEventRecord(e_fork, 0);
    cudaStreamWaitEvent(s_geo, e_fork, 0);
    geo_bias<<<dim3(NN, BB), 256, 0, s_geo>>>(box, WGw, WGb);
    cudaEventRecord(e_join, s_geo);

    gemm_qkv64<<<qkvgrid, 256>>>(xq, xk, xv, Wq, Wk, Wv, bq, bk, bv,
                                 (float*)pq, (float*)pk, (float*)pv);

    cudaStreamWaitEvent(0, e_join, 0);

    attn3<<<dim3(NN / 64, HH, BB), 256, sizeof(AttnSmem)>>>(msk);

    gemm_one64<<<ogrid, 256>>>((const float*)pa, Wo, bo, out);
}

// round 15
// speedup vs baseline: 1.0643x; 1.0643x over previous
#include <cuda_runtime.h>
#include <cuda_bf16.h>
#include <mma.h>

using namespace nvcuda;

#define BB 16
#define NN 256
#define DM 512
#define HH 8
#define DK 64

// Scratch (allocation-free rule: __device__ globals)
__device__ float g_q[BB*NN*DM];
__device__ float g_k[BB*NN*DM];
__device__ float g_v[BB*NN*DM];
__device__ float g_bias[BB*HH*NN*NN];   // clamped relu(w_g)
__device__ float g_att[BB*NN*DM];       // attention output pre-Wo

__constant__ float c_dim[8] = {
    1.0f, 0.421696503f, 0.177827941f, 0.0749894209f,
    0.0316227766f, 0.0133352143f, 0.00562341325f, 0.00237137371f};

#define GM 4096
#define GN 512
#define GK 512
#define BK2 32
#define NKT2 (GK / BK2)   // 16

// convert 8 floats -> hi/lo bf16x2 quads, one 16B STS each
__device__ __forceinline__ void cvt_store8(
    __nv_bfloat16* dst_hi, __nv_bfloat16* dst_lo, const float* v)
{
    __nv_bfloat162 h[4], l[4];
    #pragma unroll
    for (int i = 0; i < 4; i++) {
        float2 f = make_float2(v[2*i], v[2*i + 1]);
        h[i] = __float22bfloat162_rn(f);
        float2 hf = __bfloat1622float2(h[i]);
        l[i] = __float22bfloat162_rn(make_float2(f.x - hf.x, f.y - hf.y));
    }
    *reinterpret_cast<uint4*>(dst_hi) = *reinterpret_cast<const uint4*>(h);
    *reinterpret_cast<uint4*>(dst_lo) = *reinterpret_cast<const uint4*>(l);
}
__device__ __forceinline__ void cvt_store16(
    __nv_bfloat16* dst_hi, __nv_bfloat16* dst_lo, const float* v)
{
    cvt_store8(dst_hi, dst_lo, v);
    cvt_store8(dst_hi + 8, dst_lo + 8, v + 8);
}

// ---------------------------------------------------------------------------
// 64x128 GEMM tile, BK=32 (halves barrier count), bf16 3-term split,
// double-buffered dynamic smem (~55KB -> 2 CTAs/SM). NO min-blocks cap
// (R14 showed the reg-cap spills cost more than extra warps gain).
// ---------------------------------------------------------------------------
struct GemmSmem64 {
    __nv_bfloat16 Ah[64][40];    // 32 k + pad, 80B rows (16B-multiple)
    __nv_bfloat16 Al[64][40];
    __nv_bfloat16 Bh[32][136];   // 272B rows
    __nv_bfloat16 Bl[32][136];
};
#define GEMM_SMEM_BYTES ((int)(2 * sizeof(GemmSmem64)))

__device__ __forceinline__ void gemm_tile64(
    GemmSmem64* sm,
    const float* __restrict__ A, const float* __restrict__ W,
    const float* __restrict__ bias, float* __restrict__ C,
    int bm, int bn)
{
    const int tid  = threadIdx.x;
    const int warp = tid >> 5;
    const int lane = tid & 31;
    const int wm   = warp >> 2;     // 0..1 -> rows
    const int wn   = warp & 3;      // 0..3 -> cols

    const int ar = tid >> 2;              // 0..63
    const int ac = (tid & 3) * 8;         // 0,8,16,24
    const int br = tid >> 3;              // 0..31
    const int bc = (tid & 7) * 16;        // 0..112

    wmma::fragment<wmma::accumulator, 16, 16, 16, float> acc[2][2];
    #pragma unroll
    for (int i = 0; i < 2; i++)
        #pragma unroll
        for (int j = 0; j < 2; j++)
            wmma::fill_fragment(acc[i][j], 0.0f);

    float va[8], vb[16];
    // prologue: ldg k-slab 0, stage into buffer 0
    {
        const float* ap = &A[(size_t)(bm + ar) * GK + ac];
        float4 f0 = *reinterpret_cast<const float4*>(ap);
        float4 f1 = *reinterpret_cast<const float4*>(ap + 4);
        va[0]=f0.x; va[1]=f0.y; va[2]=f0.z; va[3]=f0.w;
        va[4]=f1.x; va[5]=f1.y; va[6]=f1.z; va[7]=f1.w;
        const float* bp = &W[(size_t)br * GN + bn + bc];
        #pragma unroll
        for (int g = 0; g < 4; g++) {
            float4 f = *reinterpret_cast<const float4*>(bp + g * 4);
            vb[g*4+0]=f.x; vb[g*4+1]=f.y; vb[g*4+2]=f.z; vb[g*4+3]=f.w;
        }
        cvt_store8(&sm[0].Ah[ar][ac], &sm[0].Al[ar][ac], va);
        cvt_store16(&sm[0].Bh[br][bc], &sm[0].Bl[br][bc], vb);
    }
    __syncthreads();

    for (int kt = 0; kt < NKT2; kt++) {
        const int cur = kt & 1;
        const bool more = (kt + 1 < NKT2);

        // ldg next slab (latency hidden by mma below)
        if (more) {
            const int k0 = (kt + 1) * BK2;
            const float* ap = &A[(size_t)(bm + ar) * GK + k0 + ac];
            float4 f0 = *reinterpret_cast<const float4*>(ap);
            float4 f1 = *reinterpret_cast<const float4*>(ap + 4);
            va[0]=f0.x; va[1]=f0.y; va[2]=f0.z; va[3]=f0.w;
            va[4]=f1.x; va[5]=f1.y; va[6]=f1.z; va[7]=f1.w;
            const float* bp = &W[(size_t)(k0 + br) * GN + bn + bc];
            #pragma unroll
            for (int g = 0; g < 4; g++) {
                float4 f = *reinterpret_cast<const float4*>(bp + g * 4);
                vb[g*4+0]=f.x; vb[g*4+1]=f.y; vb[g*4+2]=f.z; vb[g*4+3]=f.w;
            }
        }

        // mma on current buffer: 2 k16 steps
        {
            GemmSmem64& s = sm[cur];
            #pragma unroll
            for (int ks = 0; ks < BK2; ks += 16) {
                wmma::fragment<wmma::matrix_a, 16, 16, 16, __nv_bfloat16,
                               wmma::row_major> ah[2], al[2];
                wmma::fragment<wmma::matrix_b, 16, 16, 16, __nv_bfloat16,
                               wmma::row_major> bh[2], bl[2];
                #pragma unroll
                for (int i = 0; i < 2; i++) {
                    wmma::load_matrix_sync(ah[i], &s.Ah[wm * 32 + i * 16][ks], 40);
                    wmma::load_matrix_sync(al[i], &s.Al[wm * 32 + i * 16][ks], 40);
                }
                #pragma unroll
                for (int j = 0; j < 2; j++) {
                    wmma::load_matrix_sync(bh[j], &s.Bh[ks][wn * 32 + j * 16], 136);
                    wmma::load_matrix_sync(bl[j], &s.Bl[ks][wn * 32 + j * 16], 136);
                }
                #pragma unroll
                for (int i = 0; i < 2; i++)
                    #pragma unroll
                    for (int j = 0; j < 2; j++) {
                        wmma::mma_sync(acc[i][j], ah[i], bh[j], acc[i][j]);
                        wmma::mma_sync(acc[i][j], ah[i], bl[j], acc[i][j]);
                        wmma::mma_sync(acc[i][j], al[i], bh[j], acc[i][j]);
                    }
            }
        }

        // stage next slab into the other buffer
        if (more) {
            cvt_store8(&sm[cur ^ 1].Ah[ar][ac], &sm[cur ^ 1].Al[ar][ac], va);
            cvt_store16(&sm[cur ^ 1].Bh[br][bc], &sm[cur ^ 1].Bl[br][bc], vb);
        }
        __syncthreads();
    }

    // epilogue: per-warp fp32 smem scratch (overlays dead tile data), fused bias
    float* epib = reinterpret_cast<float*>(sm) + warp * 288;  // 16x18 floats
    const int er = lane >> 1;
    const int ec = (lane & 1) * 8;
    #pragma unroll
    for (int i = 0; i < 2; i++)
        #pragma unroll
        for (int j = 0; j < 2; j++) {
            wmma::store_matrix_sync(epib, acc[i][j], 18, wmma::mem_row_major);
            __syncwarp();
            const int row = bm + wm * 32 + i * 16 + er;
            const int col = bn + wn * 32 + j * 16 + ec;
            float4 b0 = *reinterpret_cast<const float4*>(&bias[col]);
            float4 b1 = *reinterpret_cast<const float4*>(&bias[col + 4]);
            const float* ep = &epib[er * 18 + ec];
            float4 o0 = {ep[0] + b0.x, ep[1] + b0.y, ep[2] + b0.z, ep[3] + b0.w};
            float4 o1 = {ep[4] + b1.x, ep[5] + b1.y, ep[6] + b1.z, ep[7] + b1.w};
            *reinterpret_cast<float4*>(&C[(size_t)row * GN + col])     = o0;
            *reinterpret_cast<float4*>(&C[(size_t)row * GN + col + 4]) = o1;
            __syncwarp();
        }
}

// QKV: 64x128 tiles, blockIdx.z selects triple. (4,64,3) = 768 blocks.
__global__ __launch_bounds__(256) void gemm_qkv64(
    const float* __restrict__ xq, const float* __restrict__ xk,
    const float* __restrict__ xv,
    const float* __restrict__ Wq, const float* __restrict__ Wk,
    const float* __restrict__ Wv,
    const float* __restrict__ bq, const float* __restrict__ bk,
    const float* __restrict__ bv,
    float* __restrict__ oq, float* __restrict__ ok, float* __restrict__ ov)
{
    extern __shared__ char smraw[];
    GemmSmem64* sm = reinterpret_cast<GemmSmem64*>(smraw);
    const float *A, *W, *bias;
    float* C;
    if (blockIdx.z == 0)      { A = xq; W = Wq; bias = bq; C = oq; }
    else if (blockIdx.z == 1) { A = xk; W = Wk; bias = bk; C = ok; }
    else                      { A = xv; W = Wv; bias = bv; C = ov; }
    gemm_tile64(sm, A, W, bias, C, blockIdx.y * 64, blockIdx.x * 128);
}

__global__ __launch_bounds__(256) void gemm_one64(
    const float* __restrict__ A, const float* __restrict__ W,
    const float* __restrict__ bias, float* __restrict__ C)
{
    extern __shared__ char smraw[];
    GemmSmem64* sm = reinterpret_cast<GemmSmem64*>(smraw);
    gemm_tile64(sm, A, W, bias, C, blockIdx.y * 64, blockIdx.x * 128);
}

// ---------------------------------------------------------------------------
// Geometric weights (unchanged)
// ---------------------------------------------------------------------------
__global__ __launch_bounds__(256) void geo_bias(
    const float* __restrict__ box, const float* __restrict__ WGw,
    const float* __restrict__ WGb)
{
    __shared__ float sW[HH * 64];
    __shared__ float sB[HH];
    const int b = blockIdx.y;
    const int q = blockIdx.x;
    const int m = threadIdx.x;

    sW[m] = WGw[m];
    sW[m + 256] = WGw[m + 256];
    if (m < HH) sB[m] = WGb[m];
    __syncthreads();

    const float* bq = box + ((size_t)b * NN + q) * 4;
    const float x0q = bq[0], y0q = bq[1], x1q = bq[2], y1q = bq[3];
    const float cxq = (x0q + x1q) * 0.5f, cyq = (y0q + y1q) * 0.5f;
    const float wq = x1q - x0q + 1.0f,   hq = y1q - y0q + 1.0f;

    const float* bmp = box + ((size_t)b * NN + m) * 4;
    const float x0m = bmp[0], y0m = bmp[1], x1m = bmp[2], y1m = bmp[3];
    const float cxm = (x0m + x1m) * 0.5f, cym = (y0m + y1m) * 0.5f;
    const float wm = x1m - x0m + 1.0f,    hm = y1m - y0m + 1.0f;

    float delta[4];
    delta[0] = logf(fmaxf(fabsf((cxq - cxm) / wq), 0.001f));
    delta[1] = logf(fmaxf(fabsf((cyq - cym) / hq), 0.001f));
    delta[2] = logf(wq / wm);
    delta[3] = logf(hq / hm);

    float acc[HH];
    #pragma unroll
    for (int h = 0; h < HH; h++) acc[h] = sB[h];

    #pragma unroll
    for (int p = 0; p < 4; p++) {
        #pragma unroll
        for (int f = 0; f < 8; f++) {
            float ang = 100.0f * delta[p] * c_dim[f];
            float r = ang - 6.28318530717958647692f *
                            rintf(ang * 0.15915494309189533577f);
            float s, c;
            sincosf(r, &s, &c);
            const int idx = p * 8 + f;
            #pragma unroll
            for (int h = 0; h < HH; h++)
                acc[h] += s * sW[h * 64 + idx] + c * sW[h * 64 + 32 + idx];
        }
    }

    #pragma unroll
    for (int h = 0; h < HH; h++) {
        g_bias[(((size_t)b * HH + h) * NN + q) * NN + m] =
            fmaxf(acc[h], 1e-6f);
    }
}

// ---------------------------------------------------------------------------
// Tensor-core attention with aliased smem buffers (~91KB -> 2 CTAs/SM)
// (unchanged from R13)
// ---------------------------------------------------------------------------
struct AttnSmem {
    __nv_bfloat16 Qh[64][72],  Ql[64][72];
    __nv_bfloat16 KPh[64][72], KPl[64][72];   // K tile, then P tile
    __nv_bfloat16 Vh[64][72],  Vl[64][72];
    float SOd[64][68];                        // scores, then Od
    float Os [64][68];
    float M[64], L[64], Sc[64];
};

__global__ __launch_bounds__(256, 2) void attn3(const int* __restrict__ mask)
{
    extern __shared__ char smraw[];
    AttnSmem& sm = *reinterpret_cast<AttnSmem*>(smraw);

    const int qt = blockIdx.x, h = blockIdx.y, b = blockIdx.z;
    const int qb = qt * 64;
    const int tid  = threadIdx.x;
    const int warp = tid >> 5;
    const int wm   = warp >> 2;   // 0..1
    const int wn   = warp & 3;    // 0..3
    const int rq   = tid >> 2;    // 0..63
    const int sub  = tid & 3;
    const int d0   = sub * 16;

    {
        const float* qp = g_q + ((size_t)(b * NN + qb + rq)) * DM + h * DK + d0;
        float v[16];
        #pragma unroll
        for (int g = 0; g < 4; g++) {
            float4 f = *reinterpret_cast<const float4*>(qp + g * 4);
            v[g*4+0] = f.x * 0.125f; v[g*4+1] = f.y * 0.125f;
            v[g*4+2] = f.z * 0.125f; v[g*4+3] = f.w * 0.125f;
        }
        cvt_store16(&sm.Qh[rq][d0], &sm.Ql[rq][d0], v);
    }
    if (tid < 64) { sm.M[tid] = -3.0e38f; sm.L[tid] = 0.0f; }
    #pragma unroll
    for (int j = 0; j < 16; j++) sm.Os[rq][d0 + j] = 0.0f;

    const int* mk = mask + b * NN;
    const float* wgrow = g_bias + ((size_t)(b * HH + h) * NN + qb) * NN + (size_t)rq * NN;

    for (int kt = 0; kt < 4; kt++) {
        const int kg0 = kt * 64;
        __syncthreads();
        {
            float v[16];
            const float* kp = g_k + ((size_t)(b * NN + kg0 + rq)) * DM + h * DK + d0;
            #pragma unroll
            for (int g = 0; g < 4; g++) {
                float4 f = *reinterpret_cast<const float4*>(kp + g * 4);
                v[g*4+0]=f.x; v[g*4+1]=f.y; v[g*4+2]=f.z; v[g*4+3]=f.w;
            }
            cvt_store16(&sm.KPh[rq][d0], &sm.KPl[rq][d0], v);
            const float* vp = g_v + ((size_t)(b * NN + kg0 + rq)) * DM + h * DK + d0;
            #pragma unroll
            for (int g = 0; g < 4; g++) {
                float4 f = *reinterpret_cast<const float4*>(vp + g * 4);
                v[g*4+0]=f.x; v[g*4+1]=f.y; v[g*4+2]=f.z; v[g*4+3]=f.w;
            }
            cvt_store16(&sm.Vh[rq][d0], &sm.Vl[rq][d0], v);
        }
        __syncthreads();

        // scores: S = Q·K^T
        {
            wmma::fragment<wmma::accumulator, 16, 16, 16, float> sa[2];
            #pragma unroll
            for (int i = 0; i < 2; i++) wmma::fill_fragment(sa[i], 0.0f);
            #pragma unroll
            for (int kk = 0; kk < 4; kk++) {
                wmma::fragment<wmma::matrix_b, 16, 16, 16, __nv_bfloat16,
                               wmma::col_major> bh, bl;
                wmma::load_matrix_sync(bh, &sm.KPh[wn * 16][kk * 16], 72);
                wmma::load_matrix_sync(bl, &sm.KPl[wn * 16][kk * 16], 72);
                #pragma unroll
                for (int i = 0; i < 2; i++) {
                    wmma::fragment<wmma::matrix_a, 16, 16, 16, __nv_bfloat16,
                                   wmma::row_major> ah, al;
                    wmma::load_matrix_sync(ah, &sm.Qh[wm * 32 + i * 16][kk * 16], 72);
                    wmma::load_matrix_sync(al, &sm.Ql[wm * 32 + i * 16][kk * 16], 72);
                    wmma::mma_sync(sa[i], ah, bh, sa[i]);
                    wmma::mma_sync(sa[i], ah, bl, sa[i]);
                    wmma::mma_sync(sa[i], al, bh, sa[i]);
                }
            }
            #pragma unroll
            for (int i = 0; i < 2; i++)
                wmma::store_matrix_sync(&sm.SOd[wm * 32 + i * 16][wn * 16], sa[i],
                                        68, wmma::mem_row_major);
        }
        __syncthreads();

        // online softmax: read S, write P (over K region)
        {
            const int4* mi = reinterpret_cast<const int4*>(&mk[kg0 + d0]);
            int mv[16];
            #pragma unroll
            for (int g = 0; g < 4; g++) {
                int4 m4 = mi[g];
                mv[g*4+0]=m4.x; mv[g*4+1]=m4.y; mv[g*4+2]=m4.z; mv[g*4+3]=m4.w;
            }
            float s[16];
            float mt = -3.0e38f;
            #pragma unroll
            for (int j = 0; j < 16; j++) {
                float sv = sm.SOd[rq][d0 + j];
                if (mv[j] == 0) sv = -1e9f;
                s[j] = sv;
                mt = fmaxf(mt, sv);
            }
            mt = fmaxf(mt, __shfl_xor_sync(0xffffffffu, mt, 1));
            mt = fmaxf(mt, __shfl_xor_sync(0xffffffffu, mt, 2));
            if (sub == 0) {
                float m_old = sm.M[rq];
                float m_new = fmaxf(m_old, mt);
                sm.M[rq] = m_new;
                float sc = __expf(m_old - m_new);
                sm.Sc[rq] = sc;
                sm.L[rq] *= sc;
            }
            __syncwarp();
            const float mq = sm.M[rq];
            float p[16];
            float psum = 0.0f;
            const float* wgp = wgrow + kg0 + d0;
            #pragma unroll
            for (int g = 0; g < 4; g++) {
                float4 w4 = *reinterpret_cast<const float4*>(wgp + g * 4);
                float wv[4] = {w4.x, w4.y, w4.z, w4.w};
                #pragma unroll
                for (int u = 0; u < 4; u++) {
                    float pv = wv[u] * __expf(s[g*4+u] - mq);
                    p[g*4+u] = pv;
                    psum += pv;
                }
            }
            cvt_store16(&sm.KPh[rq][d0], &sm.KPl[rq][d0], p);
            psum += __shfl_xor_sync(0xffffffffu, psum, 1);
            psum += __shfl_xor_sync(0xffffffffu, psum, 2);
            if (sub == 0) sm.L[rq] += psum;
        }
        __syncthreads();

        // PV: Od = P·V (over S region)
        {
            wmma::fragment<wmma::accumulator, 16, 16, 16, float> pa[2];
            #pragma unroll
            for (int i = 0; i < 2; i++) wmma::fill_fragment(pa[i], 0.0f);
            #pragma unroll
            for (int kk = 0; kk < 4; kk++) {
                wmma::fragment<wmma::matrix_b, 16, 16, 16, __nv_bfloat16,
                               wmma::row_major> bh, bl;
                wmma::load_matrix_sync(bh, &sm.Vh[kk * 16][wn * 16], 72);
                wmma::load_matrix_sync(bl, &sm.Vl[kk * 16][wn * 16], 72);
                #pragma unroll
                for (int i = 0; i < 2; i++) {
                    wmma::fragment<wmma::matrix_a, 16, 16, 16, __nv_bfloat16,
                                   wmma::row_major> ah, al;
                    wmma::load_matrix_sync(ah, &sm.KPh[wm * 32 + i * 16][kk * 16], 72);
                    wmma::load_matrix_sync(al, &sm.KPl[wm * 32 + i * 16][kk * 16], 72);
                    wmma::mma_sync(pa[i], ah, bh, pa[i]);
                    wmma::mma_sync(pa[i], ah, bl, pa[i]);
                    wmma::mma_sync(pa[i], al, bh, pa[i]);
                }
            }
            #pragma unroll
            for (int i = 0; i < 2; i++)
                wmma::store_matrix_sync(&sm.SOd[wm * 32 + i * 16][wn * 16], pa[i],
                                        68, wmma::mem_row_major);
        }
        __syncthreads();

        // merge: Os = Os*scale + Od
        {
            const float sc = sm.Sc[rq];
            #pragma unroll
            for (int j = 0; j < 16; j++)
                sm.Os[rq][d0 + j] = sm.Os[rq][d0 + j] * sc + sm.SOd[rq][d0 + j];
        }
    }
    __syncthreads();

    {
        const float inv = 1.0f / sm.L[rq];
        float* op = g_att + ((size_t)(b * NN + qb + rq)) * DM + h * DK + d0;
        #pragma unroll
        for (int g = 0; g < 4; g++) {
            float4 o;
            o.x = sm.Os[rq][d0 + g*4 + 0] * inv;
            o.y = sm.Os[rq][d0 + g*4 + 1] * inv;
            o.z = sm.Os[rq][d0 + g*4 + 2] * inv;
            o.w = sm.Os[rq][d0 + g*4 + 3] * inv;
            *reinterpret_cast<float4*>(op + g * 4) = o;
        }
    }
}

// ---------------------------------------------------------------------------
extern "C" void kernel_launch(void* const* d_in, const int* in_sizes, int n_in,
                              void* d_out, int out_size)
{
    const float* xq  = (const float*)d_in[0];
    const float* xk  = (const float*)d_in[1];
    const float* xv  = (const float*)d_in[2];
    const float* box = (const float*)d_in[3];
    const int*   msk = (const int*)  d_in[4];
    const float* Wq  = (const float*)d_in[5];
    const float* bq  = (const float*)d_in[6];
    const float* Wk  = (const float*)d_in[7];
    const float* bk  = (const float*)d_in[8];
    const float* Wv  = (const float*)d_in[9];
    const float* bv  = (const float*)d_in[10];
    const float* Wo  = (const float*)d_in[11];
    const float* bo  = (const float*)d_in[12];
    const float* WGw = (const float*)d_in[13];
    const float* WGb = (const float*)d_in[14];

    float* out = (float*)d_out;

    void *pq, *pk, *pv, *pa;
    cudaGetSymbolAddress(&pq, g_q);
    cudaGetSymbolAddress(&pk, g_k);
    cudaGetSymbolAddress(&pv, g_v);
    cudaGetSymbolAddress(&pa, g_att);

    static cudaStream_t s_geo = nullptr;
    static cudaEvent_t  e_fork = nullptr, e_join = nullptr;
    if (s_geo == nullptr) {
        cudaStreamCreateWithFlags(&s_geo, cudaStreamNonBlocking);
        cudaEventCreateWithFlags(&e_fork, cudaEventDisableTiming);
        cudaEventCreateWithFlags(&e_join, cudaEventDisableTiming);
        cudaFuncSetAttribute(attn3,
            cudaFuncAttributeMaxDynamicSharedMemorySize, (int)sizeof(AttnSmem));
        cudaFuncSetAttribute(gemm_qkv64,
            cudaFuncAttributeMaxDynamicSharedMemorySize, GEMM_SMEM_BYTES);
        cudaFuncSetAttribute(gemm_one64,
            cudaFuncAttributeMaxDynamicSharedMemorySize, GEMM_SMEM_BYTES);
    }

    dim3 qkvgrid(GN / 128, GM / 64, 3);     // (4, 64, 3) = 768 blocks
    dim3 ogrid  (GN / 128, GM / 64);        // (4, 64)    = 256 blocks

    cudaEventRecord(e_fork, 0);
    cudaStreamWaitEvent(s_geo, e_fork, 0);
    geo_bias<<<dim3(NN, BB), 256, 0, s_geo>>>(box, WGw, WGb);
    cudaEventRecord(e_join, s_geo);

    gemm_qkv64<<<qkvgrid, 256, GEMM_SMEM_BYTES>>>(
        xq, xk, xv, Wq, Wk, Wv, bq, bk, bv,
        (float*)pq, (float*)pk, (float*)pv);

    cudaStreamWaitEvent(0, e_join, 0);

    attn3<<<dim3(NN / 64, HH, BB), 256, sizeof(AttnSmem)>>>(msk);

    gemm_one64<<<ogrid, 256, GEMM_SMEM_BYTES>>>((const float*)pa, Wo, bo, out);
}